// round 7
// baseline (speedup 1.0000x reference)
#include <cuda_runtime.h>
#include <math.h>

// input:  (B=2, T=2048, V=32000) f32 ; target: (2, 2048) int32 ; out: scalar f32
// ct_len = 512, win = 256
#define B_DIM 2
#define T_DIM 2048
#define V_DIM 32000
#define CT_LEN 512
#define WIN 256
#define ROWS (B_DIM * CT_LEN)      // 1024
#define IGNORE_INDEX (-100)
#define PAD_ID 0

#define WARPS_PER_CTA 4
#define CTA_THREADS (WARPS_PER_CTA * 32)      // 128
#define GRID_CTAS (ROWS / WARPS_PER_CTA)      // 256
#define NEGS_PER_LANE (WIN / 32)              // 8

// Allocation-free scratch (every element rewritten each call; counter self-resets)
__device__ float        g_row_loss[ROWS];
__device__ float        g_row_valid[ROWS];
__device__ unsigned int g_done = 0u;

// L2 evict_last access policy: keep gathered sectors resident in L2 across
// graph replays. Valid PTX: createpolicy + ld.global.nc.L2::cache_hint.
__device__ __forceinline__ unsigned long long make_evict_last_policy() {
    unsigned long long pol;
    asm("createpolicy.fractional.L2::evict_last.b64 %0, 1.0;" : "=l"(pol));
    return pol;
}
__device__ __forceinline__ float ldg_el_f32(const float* p, unsigned long long pol) {
    float v;
    asm volatile("ld.global.nc.L2::cache_hint.f32 %0, [%1], %2;"
                 : "=f"(v) : "l"(p), "l"(pol));
    return v;
}
__device__ __forceinline__ int ldg_el_s32(const int* p, unsigned long long pol) {
    int v;
    asm volatile("ld.global.nc.L2::cache_hint.b32 %0, [%1], %2;"
                 : "=r"(v) : "l"(p), "l"(pol));
    return v;
}

__global__ __launch_bounds__(CTA_THREADS, 8)
void ctl_warp_kernel(const float* __restrict__ input,
                     const int* __restrict__ target,
                     float* __restrict__ out)
{
    const int tid  = threadIdx.x;
    const int lane = tid & 31;
    const int w    = tid >> 5;
    const int row  = blockIdx.x * WARPS_PER_CTA + w;  // 0..1023
    const int b    = row >> 9;                        // / CT_LEN
    const int i    = row & (CT_LEN - 1);

    const unsigned long long pol = make_evict_last_policy();

    const int tbase = b * T_DIM;
    const long long lbase = ((long long)(b * T_DIM + i)) * V_DIM;

    // --- batch 1: all target loads (coalesced) + row target (broadcast) ---
    const int t = ldg_el_s32(&target[tbase + i], pol);
    int tj[NEGS_PER_LANE];
    #pragma unroll
    for (int k = 0; k < NEGS_PER_LANE; k++) {
        const int j = i - WIN + k * 32 + lane;
        tj[k] = (j >= 0) ? ldg_el_s32(&target[tbase + j], pol) : PAD_ID;
    }

    const int vrow = (t != IGNORE_INDEX);
    int ts = vrow ? t : PAD_ID;
    ts = ts < 0 ? 0 : (ts >= V_DIM ? V_DIM - 1 : ts);

    // --- batch 2: pos (warp-broadcast) + 8 independent gathers, all in flight ---
    const float pos = ldg_el_f32(&input[lbase + ts], pol);
    float nv[NEGS_PER_LANE];
    #pragma unroll
    for (int k = 0; k < NEGS_PER_LANE; k++) {
        int c = tj[k];
        int idx = c < 0 ? 0 : (c >= V_DIM ? V_DIM - 1 : c);  // PAD/j<0 -> idx 0 (cheap broadcast)
        nv[k] = ldg_el_f32(&input[lbase + idx], pol);
    }

    // --- compute + warp reduction (no shared, no barriers in hot path) ---
    float e = 0.0f;
    #pragma unroll
    for (int k = 0; k < NEGS_PER_LANE; k++) {
        if (tj[k] != PAD_ID)                      // j<0 lanes have tj==PAD -> excluded
            e += __expf(nv[k] - pos);
    }
    #pragma unroll
    for (int o = 16; o > 0; o >>= 1)
        e += __shfl_down_sync(0xffffffffu, e, o);

    if (lane == 0) {
        g_row_loss[row]  = vrow ? log1pf(e) : 0.0f;
        g_row_valid[row] = (float)vrow;
    }

    // --- last-CTA final reduction ---
    __shared__ int s_last;
    __syncthreads();
    if (tid == 0) {
        __threadfence();
        unsigned int ticket = atomicAdd(&g_done, 1u);
        s_last = (ticket == (unsigned int)(GRID_CTAS - 1));
    }
    __syncthreads();

    if (s_last) {
        float l = 0.0f, v = 0.0f;
        #pragma unroll
        for (int k = 0; k < ROWS / CTA_THREADS; k++) {
            l += g_row_loss[tid + k * CTA_THREADS];
            v += g_row_valid[tid + k * CTA_THREADS];
        }
        #pragma unroll
        for (int o = 16; o > 0; o >>= 1) {
            l += __shfl_down_sync(0xffffffffu, l, o);
            v += __shfl_down_sync(0xffffffffu, v, o);
        }
        __shared__ float sl[WARPS_PER_CTA];
        __shared__ float sv[WARPS_PER_CTA];
        if (lane == 0) { sl[w] = l; sv[w] = v; }
        __syncthreads();
        if (tid == 0) {
            float l2 = 0.0f, v2 = 0.0f;
            #pragma unroll
            for (int q = 0; q < WARPS_PER_CTA; q++) { l2 += sl[q]; v2 += sv[q]; }
            out[0] = l2 / fmaxf(v2, 1.0f);
            g_done = 0u;                       // reset for next graph replay
        }
    }
}

extern "C" void kernel_launch(void* const* d_in, const int* in_sizes, int n_in,
                              void* d_out, int out_size)
{
    const float* input  = (const float*)d_in[0];
    const int*   target = (const int*)d_in[1];
    float*       out    = (float*)d_out;

    (void)in_sizes; (void)n_in; (void)out_size;

    ctl_warp_kernel<<<GRID_CTAS, CTA_THREADS>>>(input, target, out);
}